// round 2
// baseline (speedup 1.0000x reference)
#include <cuda_runtime.h>
#include <math_constants.h>

#define BATCH 256
#define SEQ   2048
#define IDIM  32
#define HDIM  128
#define TSA   64   // timesteps per CTA in the projection kernel

// Scratch (allocation-free rule: static __device__ arrays)
__device__ float g_xproj[(size_t)BATCH * SEQ * HDIM];   // [B][S][H], includes bi+bh
__device__ float g_hid[(size_t)SEQ * BATCH * HDIM];     // [S][B][H]

// Packed fp32x2 FMA (Blackwell): acc.lo += a.lo*b.lo ; acc.hi += a.hi*b.hi
__device__ __forceinline__ void ffma2(unsigned long long& acc,
                                      unsigned long long a,
                                      unsigned long long b) {
    asm("fma.rn.f32x2 %0, %1, %2, %0;" : "+l"(acc) : "l"(a), "l"(b));
}
__device__ __forceinline__ float f2lo(unsigned long long v) {
    return __uint_as_float((unsigned int)v);
}
__device__ __forceinline__ float f2hi(unsigned long long v) {
    return __uint_as_float((unsigned int)(v >> 32));
}
__device__ __forceinline__ unsigned long long packf2(float lo, float hi) {
    return (unsigned long long)__float_as_uint(lo) |
           ((unsigned long long)__float_as_uint(hi) << 32);
}

// Cheap accurate tanh: abs err ~1e-7, correct saturation at +-inf
__device__ __forceinline__ float tanh_fast(float x) {
    float e = __expf(2.0f * x);
    return 1.0f - 2.0f / (e + 1.0f);
}

// ---------------------------------------------------------------------------
// Kernel A: xproj[b][t][j] = sum_i x[b][t][i]*Wi[i][j] + bi[j] + bh[j]
// ---------------------------------------------------------------------------
__global__ __launch_bounds__(128) void xproj_kernel(const float* __restrict__ x,
                                                    const float* __restrict__ Wi,
                                                    const float* __restrict__ bi,
                                                    const float* __restrict__ bh) {
    const int b  = blockIdx.x;
    const int t0 = blockIdx.y * TSA;
    const int j  = threadIdx.x;            // 0..127

    __shared__ __align__(16) float xs[TSA][IDIM];

    unsigned long long w2[IDIM / 2];
#pragma unroll
    for (int i = 0; i < IDIM; i += 2)
        w2[i >> 1] = packf2(Wi[i * HDIM + j], Wi[(i + 1) * HDIM + j]);
    const float bsum = bi[j] + bh[j];

    // cooperative load of the x tile (TSA*IDIM floats, contiguous)
    const float4* xin4 = (const float4*)(x + ((size_t)b * SEQ + t0) * IDIM);
    float4* xs4 = (float4*)&xs[0][0];
    for (int idx = threadIdx.x; idx < TSA * IDIM / 4; idx += blockDim.x)
        xs4[idx] = xin4[idx];
    __syncthreads();

    float* outp = g_xproj + ((size_t)b * SEQ + t0) * HDIM + j;
#pragma unroll 2
    for (int ts = 0; ts < TSA; ts++) {
        unsigned long long a0 = 0ull, a1 = 0ull, a2 = 0ull, a3 = 0ull;
#pragma unroll
        for (int i = 0; i < IDIM; i += 8) {
            const ulonglong2 xA = *(const ulonglong2*)&xs[ts][i];
            const ulonglong2 xB = *(const ulonglong2*)&xs[ts][i + 4];
            ffma2(a0, xA.x, w2[(i >> 1) + 0]);
            ffma2(a1, xA.y, w2[(i >> 1) + 1]);
            ffma2(a2, xB.x, w2[(i >> 1) + 2]);
            ffma2(a3, xB.y, w2[(i >> 1) + 3]);
        }
        const float s = ((f2lo(a0) + f2hi(a0)) + (f2lo(a1) + f2hi(a1))) +
                        ((f2lo(a2) + f2hi(a2)) + (f2lo(a3) + f2hi(a3)));
        outp[(size_t)ts * HDIM] = s + bsum;
    }
}

// ---------------------------------------------------------------------------
// Kernel B: sequential recurrence. One CTA per 2 batch elements.
// Thread (lb, j): owns output unit j of batch 2*blockIdx.x+lb.
// Wh column j lives in 64 packed f32x2 registers. h0 double-buffered in smem,
// one barrier per step. Inner loop is 64 FFMA2 (packed along k).
// ---------------------------------------------------------------------------
__global__ __launch_bounds__(256, 1) void rnn_kernel(const float* __restrict__ Wh,
                                                     const int* __restrict__ rdp) {
    const int lb = threadIdx.x >> 7;       // local batch 0/1
    const int j  = threadIdx.x & 127;
    const int b  = blockIdx.x * 2 + lb;
    const int rd = *rdp;

    __shared__ __align__(16) float hbuf[2][2][HDIM];  // [parity][lb][j]
    hbuf[0][lb][j] = 0.f;
    hbuf[1][lb][j] = 0.f;

    unsigned long long w2[HDIM / 2];       // (Wh[k][j], Wh[k+1][j]) pairs
#pragma unroll
    for (int k = 0; k < HDIM; k += 2)
        w2[k >> 1] = packf2(Wh[k * HDIM + j], Wh[(k + 1) * HDIM + j]);

    const float* xp   = g_xproj + (size_t)b * SEQ * HDIM + j;
    float*       hout = g_hid + (size_t)b * HDIM + j;   // + t*BATCH*HDIM per step

    float hstart = 0.f, ht = 0.f, h0self = 0.f;
    float xp_next = xp[0];
    int c = 0;                                          // t % rd tracker
    __syncthreads();

    for (int t = 0; t < SEQ; t++) {
        const float xcur = xp_next;
        if (t + 1 < SEQ) xp_next = __ldg(xp + (size_t)(t + 1) * HDIM);

        const float* hrow = &hbuf[t & 1][lb][0];
        unsigned long long a0 = 0ull, a1 = 0ull, a2 = 0ull, a3 = 0ull;
#pragma unroll
        for (int k = 0; k < HDIM; k += 8) {
            const ulonglong2 hA = *(const ulonglong2*)(hrow + k);      // h[k..k+3]
            const ulonglong2 hB = *(const ulonglong2*)(hrow + k + 4);  // h[k+4..k+7]
            ffma2(a0, hA.x, w2[(k >> 1) + 0]);
            ffma2(a1, hA.y, w2[(k >> 1) + 1]);
            ffma2(a2, hB.x, w2[(k >> 1) + 2]);
            ffma2(a3, hB.y, w2[(k >> 1) + 3]);
        }
        const float dot = ((f2lo(a0) + f2hi(a0)) + (f2lo(a1) + f2hi(a1))) +
                          ((f2lo(a2) + f2hi(a2)) + (f2lo(a3) + f2hi(a3)));
        const float hn = dot + xcur;                    // biases folded into xproj

        const bool g0 = (t == 0);
        const bool g1 = (t == SEQ - 2);
        const bool g4 = (rd == 1) && !g0 && !g1;
        const bool g2 = (!g0 && !g1 && !g4 && (c == 0));

        const float add  = g1 ? hstart : (g4 ? h0self : (g2 ? ht : 0.f));
        const float cand = tanh_fast(hn + add);
        const float h0n  = g0 ? h0self : cand;
        if (g0) hstart = hn;
        if (g2) ht = hn;
        h0self = h0n;

        hout[(size_t)t * (BATCH * HDIM)] = hn;
        hbuf[(t + 1) & 1][lb][j] = h0n;

        if (++c == rd) c = 0;
        __syncthreads();
    }
}

// ---------------------------------------------------------------------------
// Kernel C: fused scores -> softmax (per reshape-group) -> weighted sum @ Wd.
// Group/output-row r covers t in [8r, 8r+8), all b. One CTA per r, warp=dt.
// ---------------------------------------------------------------------------
__global__ __launch_bounds__(256) void out_kernel(const float* __restrict__ Wa,
                                                  const float* __restrict__ ba,
                                                  const float* __restrict__ Wd,
                                                  const float* __restrict__ bd,
                                                  float* __restrict__ out) {
    const int r    = blockIdx.x;
    const int warp = threadIdx.x >> 5;     // dt 0..7
    const int lane = threadIdx.x & 31;

    __shared__ float sc[8 * BATCH];        // scores -> att, group-local index m = dt*256+b
    __shared__ float red[8];

    const float4 wa4 = ((const float4*)Wa)[lane];
    const int t = r * 8 + warp;
    const float* hbase = g_hid + (size_t)t * BATCH * HDIM;

    // pass 1: scores
    for (int b = 0; b < BATCH; b++) {
        const float4 h4 = ((const float4*)(hbase + (size_t)b * HDIM))[lane];
        float p = h4.x * wa4.x + h4.y * wa4.y + h4.z * wa4.z + h4.w * wa4.w;
#pragma unroll
        for (int o = 16; o > 0; o >>= 1) p += __shfl_xor_sync(0xffffffffu, p, o);
        if (lane == 0) sc[warp * BATCH + b] = p + ba[0];
    }
    __syncthreads();

    // softmax over all 2048 group scores
    float mx = -CUDART_INF_F;
    for (int i = threadIdx.x; i < 8 * BATCH; i += 256) mx = fmaxf(mx, sc[i]);
#pragma unroll
    for (int o = 16; o > 0; o >>= 1) mx = fmaxf(mx, __shfl_xor_sync(0xffffffffu, mx, o));
    if (lane == 0) red[warp] = mx;
    __syncthreads();
    mx = red[0];
#pragma unroll
    for (int i = 1; i < 8; i++) mx = fmaxf(mx, red[i]);
    __syncthreads();

    float sm = 0.f;
    for (int i = threadIdx.x; i < 8 * BATCH; i += 256) {
        const float e = __expf(sc[i] - mx);
        sc[i] = e;
        sm += e;
    }
#pragma unroll
    for (int o = 16; o > 0; o >>= 1) sm += __shfl_xor_sync(0xffffffffu, sm, o);
    if (lane == 0) red[warp] = sm;
    __syncthreads();
    sm = 0.f;
#pragma unroll
    for (int i = 0; i < 8; i++) sm += red[i];
    const float rinv = 1.0f / sm;
    __syncthreads();
    for (int i = threadIdx.x; i < 8 * BATCH; i += 256) sc[i] *= rinv;
    __syncthreads();

    // pass 2: out[r] = sum_m att[m] * (hid_row(m) . Wd_row(m))   (slice is L2-hot)
    float wacc = 0.f;
    for (int b = 0; b < BATCH; b++) {
        const int m = warp * BATCH + b;
        const float4 h4 = ((const float4*)(hbase + (size_t)b * HDIM))[lane];
        const float4 d4 = ((const float4*)(Wd + (size_t)m * HDIM))[lane];
        const float p = h4.x * d4.x + h4.y * d4.y + h4.z * d4.z + h4.w * d4.w;
        wacc = fmaf(sc[m], p, wacc);
    }
#pragma unroll
    for (int o = 16; o > 0; o >>= 1) wacc += __shfl_xor_sync(0xffffffffu, wacc, o);
    if (lane == 0) red[warp] = wacc;
    __syncthreads();
    if (threadIdx.x == 0) {
        float s = 0.f;
#pragma unroll
        for (int i = 0; i < 8; i++) s += red[i];
        out[r] = s + bd[0];
    }
}

// ---------------------------------------------------------------------------
extern "C" void kernel_launch(void* const* d_in, const int* in_sizes, int n_in,
                              void* d_out, int out_size) {
    const float* x  = (const float*)d_in[0];
    const float* Wi = (const float*)d_in[1];
    const float* bi = (const float*)d_in[2];
    const float* Wh = (const float*)d_in[3];
    const float* bh = (const float*)d_in[4];
    const float* Wa = (const float*)d_in[5];
    const float* ba = (const float*)d_in[6];
    const float* Wd = (const float*)d_in[7];
    const float* bd = (const float*)d_in[8];
    const int*   rd = (const int*)d_in[9];
    float* out = (float*)d_out;

    dim3 gA(BATCH, SEQ / TSA);
    xproj_kernel<<<gA, 128>>>(x, Wi, bi, bh);
    rnn_kernel<<<BATCH / 2, 256>>>(Wh, rd);
    out_kernel<<<BATCH, 256>>>(Wa, ba, Wd, bd, out);
}

// round 4
// speedup vs baseline: 1.1940x; 1.1940x over previous
#include <cuda_runtime.h>
#include <math_constants.h>

#define BATCH 256
#define SEQ   2048
#define IDIM  32
#define HDIM  128
#define TSA   64   // timesteps per CTA in the projection kernel

// Scratch (allocation-free rule: static __device__ arrays)
__device__ float g_xproj[(size_t)BATCH * SEQ * HDIM];   // [B][S][H], includes bi+bh
__device__ float g_hid[(size_t)SEQ * BATCH * HDIM];     // [S][B][H]

// Cheap accurate tanh: abs err ~1e-7, correct saturation at +-inf
__device__ __forceinline__ float tanh_fast(float x) {
    float e = __expf(2.0f * x);
    return 1.0f - 2.0f / (e + 1.0f);
}

// ---------------------------------------------------------------------------
// Kernel A: xproj[b][t][j] = sum_i x[b][t][i]*Wi[i][j] + bi[j] + bh[j]
// ---------------------------------------------------------------------------
__global__ __launch_bounds__(128) void xproj_kernel(const float* __restrict__ x,
                                                    const float* __restrict__ Wi,
                                                    const float* __restrict__ bi,
                                                    const float* __restrict__ bh) {
    const int b  = blockIdx.x;
    const int t0 = blockIdx.y * TSA;
    const int j  = threadIdx.x;            // 0..127

    __shared__ __align__(16) float xs[TSA][IDIM];

    float w[IDIM];
#pragma unroll
    for (int i = 0; i < IDIM; i++) w[i] = Wi[i * HDIM + j];
    const float bsum = bi[j] + bh[j];

    // cooperative load of the x tile (TSA*IDIM floats, contiguous)
    const float4* xin4 = (const float4*)(x + ((size_t)b * SEQ + t0) * IDIM);
    float4* xs4 = (float4*)&xs[0][0];
    for (int idx = threadIdx.x; idx < TSA * IDIM / 4; idx += blockDim.x)
        xs4[idx] = xin4[idx];
    __syncthreads();

    float* outp = g_xproj + ((size_t)b * SEQ + t0) * HDIM + j;
#pragma unroll 2
    for (int ts = 0; ts < TSA; ts++) {
        float a0 = bsum, a1 = 0.f, a2 = 0.f, a3 = 0.f;
#pragma unroll
        for (int i = 0; i < IDIM; i += 4) {
            a0 = fmaf(xs[ts][i + 0], w[i + 0], a0);
            a1 = fmaf(xs[ts][i + 1], w[i + 1], a1);
            a2 = fmaf(xs[ts][i + 2], w[i + 2], a2);
            a3 = fmaf(xs[ts][i + 3], w[i + 3], a3);
        }
        outp[(size_t)ts * HDIM] = (a0 + a1) + (a2 + a3);
    }
}

// ---------------------------------------------------------------------------
// Kernel B: sequential recurrence. ONE batch per 128-thread CTA, grid=BATCH.
// Most SMs carry 2 independent CTAs -> independent barrier domains, so one
// CTA's reduce/tanh/BAR tail overlaps the other CTA's FFMA stream.
// Thread j owns output unit j. Wh column j in 128 registers. h0 double-
// buffered in smem, one barrier per step.
// ---------------------------------------------------------------------------
__global__ __launch_bounds__(128, 2) void rnn_kernel(const float* __restrict__ Wh,
                                                     const int* __restrict__ rdp) {
    const int j = threadIdx.x;             // 0..127
    const int b = blockIdx.x;
    const int rd = *rdp;

    __shared__ __align__(16) float hbuf[2][HDIM];  // [parity][j]
    hbuf[0][j] = 0.f;
    hbuf[1][j] = 0.f;

    float w[HDIM];
#pragma unroll
    for (int k = 0; k < HDIM; k++) w[k] = Wh[k * HDIM + j];

    const float* xp   = g_xproj + (size_t)b * SEQ * HDIM + j;
    float*       hout = g_hid + (size_t)b * HDIM + j;   // + t*BATCH*HDIM per step

    float hstart = 0.f, ht = 0.f, h0self = 0.f;
    float xp_next = xp[0];
    int c = 0;                                          // t % rd tracker
    __syncthreads();

    for (int t = 0; t < SEQ; t++) {
        const float xcur = xp_next;
        if (t + 1 < SEQ) xp_next = __ldg(xp + (size_t)(t + 1) * HDIM);

        const float* hrow = &hbuf[t & 1][0];
        float a0 = 0.f, a1 = 0.f, a2 = 0.f, a3 = 0.f;
#pragma unroll
        for (int k = 0; k < HDIM; k += 4) {
            const float4 h4 = *(const float4*)(hrow + k);
            a0 = fmaf(h4.x, w[k + 0], a0);
            a1 = fmaf(h4.y, w[k + 1], a1);
            a2 = fmaf(h4.z, w[k + 2], a2);
            a3 = fmaf(h4.w, w[k + 3], a3);
        }
        const float hn = ((a0 + a1) + (a2 + a3)) + xcur;  // biases folded into xproj

        const bool g0 = (t == 0);
        const bool g1 = (t == SEQ - 2);
        const bool g4 = (rd == 1) && !g0 && !g1;
        const bool g2 = (!g0 && !g1 && !g4 && (c == 0));

        const float add  = g1 ? hstart : (g4 ? h0self : (g2 ? ht : 0.f));
        const float cand = tanh_fast(hn + add);
        const float h0n  = g0 ? h0self : cand;
        if (g0) hstart = hn;
        if (g2) ht = hn;
        h0self = h0n;

        hout[(size_t)t * (BATCH * HDIM)] = hn;
        hbuf[(t + 1) & 1][j] = h0n;

        if (++c == rd) c = 0;
        __syncthreads();
    }
}

// ---------------------------------------------------------------------------
// Kernel C: fused scores -> softmax (per reshape-group) -> weighted sum @ Wd.
// Group/output-row r covers t in [8r, 8r+8), all b. One CTA per r, warp=dt.
// ---------------------------------------------------------------------------
__global__ __launch_bounds__(256) void out_kernel(const float* __restrict__ Wa,
                                                  const float* __restrict__ ba,
                                                  const float* __restrict__ Wd,
                                                  const float* __restrict__ bd,
                                                  float* __restrict__ out) {
    const int r    = blockIdx.x;
    const int warp = threadIdx.x >> 5;     // dt 0..7
    const int lane = threadIdx.x & 31;

    __shared__ float sc[8 * BATCH];        // scores -> att, group-local index m = dt*256+b
    __shared__ float red[8];

    const float4 wa4 = ((const float4*)Wa)[lane];
    const int t = r * 8 + warp;
    const float* hbase = g_hid + (size_t)t * BATCH * HDIM;

    // pass 1: scores
    for (int b = 0; b < BATCH; b++) {
        const float4 h4 = ((const float4*)(hbase + (size_t)b * HDIM))[lane];
        float p = h4.x * wa4.x + h4.y * wa4.y + h4.z * wa4.z + h4.w * wa4.w;
#pragma unroll
        for (int o = 16; o > 0; o >>= 1) p += __shfl_xor_sync(0xffffffffu, p, o);
        if (lane == 0) sc[warp * BATCH + b] = p + ba[0];
    }
    __syncthreads();

    // softmax over all 2048 group scores
    float mx = -CUDART_INF_F;
    for (int i = threadIdx.x; i < 8 * BATCH; i += 256) mx = fmaxf(mx, sc[i]);
#pragma unroll
    for (int o = 16; o > 0; o >>= 1) mx = fmaxf(mx, __shfl_xor_sync(0xffffffffu, mx, o));
    if (lane == 0) red[warp] = mx;
    __syncthreads();
    mx = red[0];
#pragma unroll
    for (int i = 1; i < 8; i++) mx = fmaxf(mx, red[i]);
    __syncthreads();

    float sm = 0.f;
    for (int i = threadIdx.x; i < 8 * BATCH; i += 256) {
        const float e = __expf(sc[i] - mx);
        sc[i] = e;
        sm += e;
    }
#pragma unroll
    for (int o = 16; o > 0; o >>= 1) sm += __shfl_xor_sync(0xffffffffu, sm, o);
    if (lane == 0) red[warp] = sm;
    __syncthreads();
    sm = 0.f;
#pragma unroll
    for (int i = 0; i < 8; i++) sm += red[i];
    const float rinv = 1.0f / sm;
    __syncthreads();
    for (int i = threadIdx.x; i < 8 * BATCH; i += 256) sc[i] *= rinv;
    __syncthreads();

    // pass 2: out[r] = sum_m att[m] * (hid_row(m) . Wd_row(m))   (slice is L2-hot)
    float wacc = 0.f;
    for (int b = 0; b < BATCH; b++) {
        const int m = warp * BATCH + b;
        const float4 h4 = ((const float4*)(hbase + (size_t)b * HDIM))[lane];
        const float4 d4 = ((const float4*)(Wd + (size_t)m * HDIM))[lane];
        const float p = h4.x * d4.x + h4.y * d4.y + h4.z * d4.z + h4.w * d4.w;
        wacc = fmaf(sc[m], p, wacc);
    }
#pragma unroll
    for (int o = 16; o > 0; o >>= 1) wacc += __shfl_xor_sync(0xffffffffu, wacc, o);
    if (lane == 0) red[warp] = wacc;
    __syncthreads();
    if (threadIdx.x == 0) {
        float s = 0.f;
#pragma unroll
        for (int i = 0; i < 8; i++) s += red[i];
        out[r] = s + bd[0];
    }
}

// ---------------------------------------------------------------------------
extern "C" void kernel_launch(void* const* d_in, const int* in_sizes, int n_in,
                              void* d_out, int out_size) {
    const float* x  = (const float*)d_in[0];
    const float* Wi = (const float*)d_in[1];
    const float* bi = (const float*)d_in[2];
    const float* Wh = (const float*)d_in[3];
    const float* bh = (const float*)d_in[4];
    const float* Wa = (const float*)d_in[5];
    const float* ba = (const float*)d_in[6];
    const float* Wd = (const float*)d_in[7];
    const float* bd = (const float*)d_in[8];
    const int*   rd = (const int*)d_in[9];
    float* out = (float*)d_out;

    dim3 gA(BATCH, SEQ / TSA);
    xproj_kernel<<<gA, 128>>>(x, Wi, bi, bh);
    rnn_kernel<<<BATCH, 128>>>(Wh, rd);
    out_kernel<<<BATCH, 256>>>(Wa, ba, Wd, bd, out);
}